// round 8
// baseline (speedup 1.0000x reference)
#include <cuda_runtime.h>
#include <cuda_bf16.h>
#include <math.h>
#include <stdint.h>

// Fixed problem shapes
#define M_TOT 8192
#define NREL  64
#define D     128
#define TM    32            // m per tile -> 64 A rows (u rows 0..31, v rows 32..63)
#define MAXT  320           // sum ceil(cnt/32) <= 8192/32 + 64
#define THREADS 128
#define REG_LAMBDA 1e-5f

// ---------------- device scratch (zero-init at load; reset each call) ----------------
__device__ int   g_cnt[NREL];
__device__ int4  g_bucket4[NREL * M_TOT];    // {m, h[m], pos[m], neg[m]}
__device__ int4  g_ttab[MAXT];               // {rel, start, cnt, 0}
__device__ float g_rsq[NREL];
__device__ float g_val[M_TOT];
__device__ unsigned int g_done;
__device__ unsigned int g_prep_done;
// B fragments in mma.m16n8k16 register layout:
// g_bfrag[((rel*8 + ks)*16 + nt)*32 + lane] = {b0_hi, b1_hi, b0_lo, b1_lo}
__device__ uint4 g_bfrag[NREL * 8 * 16 * 32];

// ---------------- helpers ----------------
static __device__ __forceinline__ void split_bf(float x, unsigned short& hi, unsigned short& lo) {
    __nv_bfloat16 h = __float2bfloat16(x);
    float hf = __bfloat162float(h);
    __nv_bfloat16 l = __float2bfloat16(x - hf);
    hi = __bfloat16_as_ushort(h);
    lo = __bfloat16_as_ushort(l);
}

static __device__ __forceinline__ void mma_bf16(float c[4],
                                                uint32_t a0, uint32_t a1,
                                                uint32_t a2, uint32_t a3,
                                                uint32_t b0, uint32_t b1) {
    asm("mma.sync.aligned.m16n8k16.row.col.f32.bf16.bf16.f32 "
        "{%0,%1,%2,%3}, {%4,%5,%6,%7}, {%8,%9}, {%0,%1,%2,%3};"
        : "+f"(c[0]), "+f"(c[1]), "+f"(c[2]), "+f"(c[3])
        : "r"(a0), "r"(a1), "r"(a2), "r"(a3), "r"(b0), "r"(b1));
}

// ---------------- prep: scatter (blocks 0-31) + W fragments (32-287) + table (last) ----------------
#define PREP_BLKS 288

__global__ void k_prep(const int* __restrict__ r,
                       const int* __restrict__ h,
                       const int* __restrict__ pos_t,
                       const int* __restrict__ neg_t,
                       const float* __restrict__ rel_w,
                       const float* __restrict__ rel_emb) {
    __shared__ int scnt[NREL];
    __shared__ int sbase[NREL];
    __shared__ int scur[NREL];
    int b = blockIdx.x;
    int tid = threadIdx.x;     // 256 threads

    if (b < 32) {
        // batched bucket scatter with pre-gathered indices (coalesced h/p/n reads)
        if (tid < NREL) { scnt[tid] = 0; scur[tid] = 0; }
        __syncthreads();
        int m  = b * 256 + tid;
        int rl = r[m];
        int hm = h[m], pm = pos_t[m], nm = neg_t[m];
        atomicAdd(&scnt[rl], 1);
        __syncthreads();
        if (tid < NREL && scnt[tid] > 0) sbase[tid] = atomicAdd(&g_cnt[tid], scnt[tid]);
        __syncthreads();
        int p = sbase[rl] + atomicAdd(&scur[rl], 1);
        g_bucket4[rl * M_TOT + p] = make_int4(m, hm, pm, nm);
    } else {
        // fragment build: 262144 entries over 65536 threads -> 4 per thread
        int base = (b - 32) * 256 + tid;
        #pragma unroll
        for (int q = 0; q < 4; q++) {
            int e = base + q * 65536;
            int lane = e & 31;
            int nt   = (e >> 5) & 15;
            int ks   = (e >> 9) & 7;
            int rel  = e >> 12;
            int gid = lane >> 2, tig = lane & 3;
            int j  = 8 * nt + gid;
            int k0 = 16 * ks + 2 * tig;
            const float* W = rel_w + (size_t)rel * D * D;
            float w00 = __ldg(W + k0 * D + j);
            float w01 = __ldg(W + (k0 + 1) * D + j);
            float w10 = __ldg(W + (k0 + 8) * D + j);
            float w11 = __ldg(W + (k0 + 9) * D + j);
            unsigned short h00, l00, h01, l01, h10, l10, h11, l11;
            split_bf(w00, h00, l00); split_bf(w01, h01, l01);
            split_bf(w10, h10, l10); split_bf(w11, h11, l11);
            uint4 v;
            v.x = (uint32_t)h00 | ((uint32_t)h01 << 16);
            v.y = (uint32_t)h10 | ((uint32_t)h11 << 16);
            v.z = (uint32_t)l00 | ((uint32_t)l01 << 16);
            v.w = (uint32_t)l10 | ((uint32_t)l11 << 16);
            g_bfrag[e] = v;
        }
    }

    // last prep block builds the tile table + per-rel rsq
    __shared__ bool last;
    __threadfence();
    __syncthreads();
    if (tid == 0) last = (atomicAdd(&g_prep_done, 1u) == PREP_BLKS - 1);
    __syncthreads();
    if (!last) return;
    __threadfence();

    if (tid < NREL) scnt[tid] = g_cnt[tid];
    __syncthreads();
    if (tid == 0) {
        int nt = 0;
        for (int rel = 0; rel < NREL; rel++) {
            int c = scnt[rel];
            for (int s = 0; s < c; s += TM) {
                g_ttab[nt] = make_int4(rel, s, min(TM, c - s), 0);
                nt++;
            }
        }
        for (; nt < MAXT; nt++) g_ttab[nt] = make_int4(-1, 0, 0, 0);
        g_prep_done = 0;                  // reset for next graph replay
    }
    if (tid < NREL) {
        float s = 0.f;
        const float* re = rel_emb + tid * D;
        #pragma unroll 4
        for (int i = 0; i < D; i++) { float x = re[i]; s += x * x; }
        g_rsq[tid] = s;
    }
}

// ---------------- main kernel: 320 blocks x 128 threads, static tile per block ----------------
#define ASTRIDE 264
#define NROWS   64                         // 2*TM
#define OFF_AHI 0                          // 64*264 = 16896
#define OFF_ALO 16896                      // -> 33792
#define OFF_RSH 33792                      // 512
#define OFF_SC  34304                      // 256 (64 floats)
#define OFF_REG 34560                      // 128 (32 floats)
#define OFF_MSH 34688                      // 128
#define SMEM_SZ 34816

__global__ void __launch_bounds__(THREADS, 3) k_main(
    const float* __restrict__ ent,
    const float* __restrict__ rel_emb,
    float*       __restrict__ out)
{
    extern __shared__ char smem[];
    int tid = threadIdx.x;
    int w = tid >> 5, l = tid & 31;
    int gid = l >> 2, tig = l & 3;

    float* rsh   = (float*)(smem + OFF_RSH);
    float* sc    = (float*)(smem + OFF_SC);
    float* regsh = (float*)(smem + OFF_REG);
    int*   msh   = (int*)(smem + OFF_MSH);

    int4 td = g_ttab[blockIdx.x];
    int rel = td.x, start = td.y, cnt = td.z;

    if (rel >= 0) {
        // stage indices (pre-gathered int4) + relation embedding
        int hI = 0, pI = 0, nI = 0;
        if (tid < TM) {
            if (tid < cnt) {
                int4 b4 = g_bucket4[rel * M_TOT + start + tid];
                msh[tid] = b4.x; hI = b4.y; pI = b4.z; nI = b4.w;
            }
        }
        rsh[tid] = rel_emb[rel * D + tid];
        // broadcast indices within warp halves via smem (simplest): store to sc area temporarily
        if (tid < TM) { ((int*)sc)[tid] = hI; ((int*)sc)[TM + tid] = pI; }
        if (tid < TM) { ((int*)regsh)[tid] = nI; }
        __syncthreads();

        // ---- gather + bf16 split + stage A (u at row m, v at row 32+m) ----
        float sqa[8];
        #pragma unroll
        for (int it = 0; it < 8; it++) {
            int m = w * 8 + it;
            char* puh = smem + OFF_AHI + m * ASTRIDE + 8 * l;
            char* pul = smem + OFF_ALO + m * ASTRIDE + 8 * l;
            char* pvh = smem + OFF_AHI + (TM + m) * ASTRIDE + 8 * l;
            char* pvl = smem + OFF_ALO + (TM + m) * ASTRIDE + 8 * l;
            float sq = 0.f;
            if (m < cnt) {
                int hm = ((int*)sc)[m], pm = ((int*)sc)[TM + m], nm = ((int*)regsh)[m];
                float4 h4 = ((const float4*)(ent + (size_t)hm * D))[l];
                float4 p4 = ((const float4*)(ent + (size_t)pm * D))[l];
                float4 n4 = ((const float4*)(ent + (size_t)nm * D))[l];
                float u0 = h4.x - p4.x, u1 = h4.y - p4.y, u2 = h4.z - p4.z, u3 = h4.w - p4.w;
                float v0 = h4.x - n4.x, v1 = h4.y - n4.y, v2 = h4.z - n4.z, v3 = h4.w - n4.w;
                sq = h4.x*h4.x + h4.y*h4.y + h4.z*h4.z + h4.w*h4.w
                   + p4.x*p4.x + p4.y*p4.y + p4.z*p4.z + p4.w*p4.w
                   + n4.x*n4.x + n4.y*n4.y + n4.z*n4.z + n4.w*n4.w;
                unsigned short uh[4], ul[4], vh[4], vl[4];
                split_bf(u0, uh[0], ul[0]); split_bf(u1, uh[1], ul[1]);
                split_bf(u2, uh[2], ul[2]); split_bf(u3, uh[3], ul[3]);
                split_bf(v0, vh[0], vl[0]); split_bf(v1, vh[1], vl[1]);
                split_bf(v2, vh[2], vl[2]); split_bf(v3, vh[3], vl[3]);
                *(uint2*)puh = make_uint2((uint32_t)uh[0] | ((uint32_t)uh[1] << 16),
                                          (uint32_t)uh[2] | ((uint32_t)uh[3] << 16));
                *(uint2*)pul = make_uint2((uint32_t)ul[0] | ((uint32_t)ul[1] << 16),
                                          (uint32_t)ul[2] | ((uint32_t)ul[3] << 16));
                *(uint2*)pvh = make_uint2((uint32_t)vh[0] | ((uint32_t)vh[1] << 16),
                                          (uint32_t)vh[2] | ((uint32_t)vh[3] << 16));
                *(uint2*)pvl = make_uint2((uint32_t)vl[0] | ((uint32_t)vl[1] << 16),
                                          (uint32_t)vl[2] | ((uint32_t)vl[3] << 16));
            } else {
                uint2 z = make_uint2(0u, 0u);
                *(uint2*)puh = z; *(uint2*)pul = z;
                *(uint2*)pvh = z; *(uint2*)pvl = z;
            }
            sqa[it] = sq;
        }
        __syncthreads();   // indices in sc/regsh consumed; A staged

        // reg squares: shfl-reduce each row, write regsh
        #pragma unroll
        for (int it = 0; it < 8; it++) {
            float s = sqa[it];
            #pragma unroll
            for (int o = 16; o; o >>= 1) s += __shfl_xor_sync(0xffffffffu, s, o);
            if (l == 0) regsh[w * 8 + it] = s;
        }

        // ---- MMA: warp w computes rows 16w..16w+15, all 128 cols (3-pass bf16 split) ----
        const char* A0h = smem + OFF_AHI + (16 * w + gid) * ASTRIDE + 4 * tig;
        const char* A1h = A0h + 8 * ASTRIDE;
        const char* A0l = smem + OFF_ALO + (16 * w + gid) * ASTRIDE + 4 * tig;
        const char* A1l = A0l + 8 * ASTRIDE;

        float c[16][4];
        #pragma unroll
        for (int nt = 0; nt < 16; nt++)
            #pragma unroll
            for (int i = 0; i < 4; i++) c[nt][i] = 0.f;

        for (int ks = 0; ks < 8; ks++) {
            uint32_t ah0 = *(const uint32_t*)(A0h + 32 * ks);
            uint32_t ah1 = *(const uint32_t*)(A1h + 32 * ks);
            uint32_t ah2 = *(const uint32_t*)(A0h + 32 * ks + 16);
            uint32_t ah3 = *(const uint32_t*)(A1h + 32 * ks + 16);
            uint32_t al0 = *(const uint32_t*)(A0l + 32 * ks);
            uint32_t al1 = *(const uint32_t*)(A1l + 32 * ks);
            uint32_t al2 = *(const uint32_t*)(A0l + 32 * ks + 16);
            uint32_t al3 = *(const uint32_t*)(A1l + 32 * ks + 16);

            const uint4* bp = g_bfrag + ((size_t)(rel * 8 + ks) * 16) * 32 + l;
            uint4 b[16];
            #pragma unroll
            for (int nt = 0; nt < 16; nt++) b[nt] = bp[nt * 32];   // MLP=16, L2-hot

            #pragma unroll
            for (int nt = 0; nt < 16; nt++) {
                mma_bf16(c[nt], ah0, ah1, ah2, ah3, b[nt].x, b[nt].y);
                mma_bf16(c[nt], ah0, ah1, ah2, ah3, b[nt].z, b[nt].w);
                mma_bf16(c[nt], al0, al1, al2, al3, b[nt].x, b[nt].y);
            }
        }

        // ---- epilogue: add r_j, square, reduce over j ----
        float sA = 0.f, sB = 0.f;        // rows 16w+gid, 16w+8+gid
        #pragma unroll
        for (int nt = 0; nt < 16; nt++) {
            float r0 = rsh[8 * nt + 2 * tig];
            float r1 = rsh[8 * nt + 2 * tig + 1];
            float d0 = c[nt][0] + r0, d1 = c[nt][1] + r1;
            float d2 = c[nt][2] + r0, d3 = c[nt][3] + r1;
            sA += d0 * d0 + d1 * d1;
            sB += d2 * d2 + d3 * d3;
        }
        sA += __shfl_xor_sync(0xffffffffu, sA, 1);
        sA += __shfl_xor_sync(0xffffffffu, sA, 2);
        sB += __shfl_xor_sync(0xffffffffu, sB, 1);
        sB += __shfl_xor_sync(0xffffffffu, sB, 2);
        if (tig == 0) {
            sc[16 * w + gid]     = sA;
            sc[16 * w + 8 + gid] = sB;
        }
        __syncthreads();

        if (tid < TM && tid < cnt) {
            float x = 0.5f * (sc[tid] - sc[TM + tid]);              // pos - neg score
            float loss = fmaxf(-x, 0.f) + log1pf(expf(-fabsf(x)));  // softplus(-x)
            g_val[msh[tid]] = loss + REG_LAMBDA * 0.5f * (regsh[tid] + g_rsq[rel]);
        }
    }

    // ---------- last-block deterministic reduction + state reset ----------
    __shared__ bool amLast;
    __threadfence();
    __syncthreads();
    if (tid == 0) {
        unsigned int prev = atomicAdd(&g_done, 1u);
        amLast = (prev == (unsigned int)(gridDim.x - 1));
    }
    __syncthreads();
    if (!amLast) return;
    __threadfence();

    double* sd = (double*)smem;
    double acc = 0.0;
    for (int i = tid; i < M_TOT; i += THREADS) acc += (double)g_val[i];
    sd[tid] = acc;
    __syncthreads();
    for (int s = THREADS / 2; s; s >>= 1) {
        if (tid < s) sd[tid] += sd[tid + s];
        __syncthreads();
    }
    if (tid == 0) out[0] = (float)(sd[0] / (double)M_TOT);

    if (tid < NREL) g_cnt[tid] = 0;
    if (tid == 0) g_done = 0;
}

// ---------------- launch ----------------
extern "C" void kernel_launch(void* const* d_in, const int* in_sizes, int n_in,
                              void* d_out, int out_size) {
    const int*   h       = (const int*)d_in[0];
    const int*   r       = (const int*)d_in[1];
    const int*   pos_t   = (const int*)d_in[2];
    const int*   neg_t   = (const int*)d_in[3];
    const float* ent     = (const float*)d_in[4];
    const float* rel_emb = (const float*)d_in[5];
    const float* rel_w   = (const float*)d_in[6];
    float* out = (float*)d_out;

    cudaFuncSetAttribute(k_main, cudaFuncAttributeMaxDynamicSharedMemorySize, SMEM_SZ);

    k_prep<<<PREP_BLKS, 256>>>(r, h, pos_t, neg_t, rel_w, rel_emb);
    k_main<<<MAXT, THREADS, SMEM_SZ>>>(ent, rel_emb, out);
}

// round 9
// speedup vs baseline: 1.1822x; 1.1822x over previous
#include <cuda_runtime.h>
#include <cuda_bf16.h>
#include <math.h>
#include <stdint.h>

// Fixed problem shapes
#define M_TOT 8192
#define NREL  64
#define D     128
#define TM    32            // m per tile -> 64 A rows (u rows 0..31, v rows 32..63)
#define MAXT  320           // sum ceil(cnt/32) <= 8192/32 + 64
#define THREADS 128
#define REG_LAMBDA 1e-5f

// ---------------- device scratch (zero-init at load; reset each call) ----------------
__device__ int   g_cnt[NREL];
__device__ int4  g_bucket4[NREL * M_TOT];    // {m, h[m], pos[m], neg[m]}
__device__ int4  g_ttab[MAXT];               // {rel, start, cnt, 0}
__device__ float g_rsq[NREL];
__device__ float g_val[M_TOT];
__device__ unsigned int g_done;
__device__ unsigned int g_scat_done;
// B fragments in mma.m16n8k16 register layout:
// g_bfrag[((rel*8 + ks)*16 + nt)*32 + lane] = {b0_hi, b1_hi, b0_lo, b1_lo}
__device__ uint4 g_bfrag[NREL * 8 * 16 * 32];

// ---------------- helpers ----------------
static __device__ __forceinline__ void split_bf(float x, unsigned short& hi, unsigned short& lo) {
    __nv_bfloat16 h = __float2bfloat16(x);
    float hf = __bfloat162float(h);
    __nv_bfloat16 l = __float2bfloat16(x - hf);
    hi = __bfloat16_as_ushort(h);
    lo = __bfloat16_as_ushort(l);
}

static __device__ __forceinline__ void mma_bf16(float c[4],
                                                uint32_t a0, uint32_t a1,
                                                uint32_t a2, uint32_t a3,
                                                uint32_t b0, uint32_t b1) {
    asm("mma.sync.aligned.m16n8k16.row.col.f32.bf16.bf16.f32 "
        "{%0,%1,%2,%3}, {%4,%5,%6,%7}, {%8,%9}, {%0,%1,%2,%3};"
        : "+f"(c[0]), "+f"(c[1]), "+f"(c[2]), "+f"(c[3])
        : "r"(a0), "r"(a1), "r"(a2), "r"(a3), "r"(b0), "r"(b1));
}

// ---------------- prep: scatter+table (blocks 0-31) + W fragments (blocks 32-95) ----------------
#define PREP_BLKS 96
#define PREP_SMEM 65536

__global__ void k_prep(const int* __restrict__ r,
                       const int* __restrict__ h,
                       const int* __restrict__ pos_t,
                       const int* __restrict__ neg_t,
                       const float* __restrict__ rel_w,
                       const float* __restrict__ rel_emb) {
    extern __shared__ char psm[];
    int b = blockIdx.x;
    int tid = threadIdx.x;     // 256 threads

    if (b < 32) {
        // ---- batched bucket scatter with pre-gathered indices ----
        int* scnt  = (int*)psm;
        int* sbase = scnt + NREL;
        int* scur  = sbase + NREL;
        if (tid < NREL) { scnt[tid] = 0; scur[tid] = 0; }
        __syncthreads();
        int m  = b * 256 + tid;
        int rl = r[m];
        int hm = h[m], pm = pos_t[m], nm = neg_t[m];
        atomicAdd(&scnt[rl], 1);
        __syncthreads();
        if (tid < NREL && scnt[tid] > 0) sbase[tid] = atomicAdd(&g_cnt[tid], scnt[tid]);
        __syncthreads();
        int p = sbase[rl] + atomicAdd(&scur[rl], 1);
        g_bucket4[rl * M_TOT + p] = make_int4(m, hm, pm, nm);

        // last scatter block builds the tile table (parallel) + per-rel rsq
        __shared__ bool last;
        __threadfence();
        __syncthreads();
        if (tid == 0) last = (atomicAdd(&g_scat_done, 1u) == 31u);
        __syncthreads();
        if (!last) return;
        __threadfence();

        int* stoff = scur + NREL;           // reuse smem
        __shared__ int s_ntiles;
        if (tid < NREL) scnt[tid] = g_cnt[tid];
        __syncthreads();
        if (tid == 0) {
            int toff = 0;
            for (int rel = 0; rel < NREL; rel++) {
                stoff[rel] = toff;
                toff += (scnt[rel] + TM - 1) / TM;
            }
            s_ntiles = toff;
            g_scat_done = 0;                // reset for next replay
        }
        __syncthreads();
        if (tid < NREL) {
            int c = scnt[tid], to = stoff[tid];
            for (int s = 0; s < c; s += TM)
                g_ttab[to++] = make_int4(tid, s, min(TM, c - s), 0);
            // per-rel rsq
            float s2 = 0.f;
            const float* re = rel_emb + tid * D;
            #pragma unroll 8
            for (int i = 0; i < D; i++) { float x = re[i]; s2 += x * x; }
            g_rsq[tid] = s2;
        }
        for (int i = s_ntiles + tid; i < MAXT; i += 256)
            g_ttab[i] = make_int4(-1, 0, 0, 0);
        return;
    }

    // ---- W fragment build: one rel per block, staged through smem ----
    {
        int rel = b - 32;
        float* Wsh = (float*)psm;           // 64 KB: W[k][j]
        const float4* src = (const float4*)(rel_w + (size_t)rel * D * D);
        float4* dst = (float4*)Wsh;
        #pragma unroll
        for (int i = tid; i < D * D / 4; i += 256) dst[i] = src[i];   // coalesced
        __syncthreads();

        // 4096 entries per rel, 16 per thread
        #pragma unroll
        for (int q = 0; q < 16; q++) {
            int e = q * 256 + tid;
            int lane = e & 31;
            int nt   = (e >> 5) & 15;
            int ks   = e >> 9;
            int gid = lane >> 2, tig = lane & 3;
            int j  = 8 * nt + gid;
            int k0 = 16 * ks + 2 * tig;
            float w00 = Wsh[k0 * D + j];
            float w01 = Wsh[(k0 + 1) * D + j];
            float w10 = Wsh[(k0 + 8) * D + j];
            float w11 = Wsh[(k0 + 9) * D + j];
            unsigned short h00, l00, h01, l01, h10, l10, h11, l11;
            split_bf(w00, h00, l00); split_bf(w01, h01, l01);
            split_bf(w10, h10, l10); split_bf(w11, h11, l11);
            uint4 v;
            v.x = (uint32_t)h00 | ((uint32_t)h01 << 16);
            v.y = (uint32_t)h10 | ((uint32_t)h11 << 16);
            v.z = (uint32_t)l00 | ((uint32_t)l01 << 16);
            v.w = (uint32_t)l10 | ((uint32_t)l11 << 16);
            g_bfrag[(size_t)rel * 4096 + e] = v;     // coalesced STG.128
        }
    }
}

// ---------------- main kernel: 320 blocks x 128 threads, static tile per block ----------------
#define ASTRIDE 264
#define OFF_AHI 0                          // 64*264 = 16896
#define OFF_ALO 16896                      // -> 33792
#define OFF_RSH 33792                      // 512
#define OFF_SC  34304                      // 256 (64 floats)
#define OFF_REG 34560                      // 128 (32 floats)
#define OFF_MSH 34688                      // 128
#define SMEM_SZ 34816

__global__ void __launch_bounds__(THREADS, 3) k_main(
    const float* __restrict__ ent,
    const float* __restrict__ rel_emb,
    float*       __restrict__ out)
{
    extern __shared__ char smem[];
    int tid = threadIdx.x;
    int w = tid >> 5, l = tid & 31;
    int gid = l >> 2, tig = l & 3;

    float* rsh   = (float*)(smem + OFF_RSH);
    float* sc    = (float*)(smem + OFF_SC);
    float* regsh = (float*)(smem + OFF_REG);
    int*   msh   = (int*)(smem + OFF_MSH);

    int4 td = g_ttab[blockIdx.x];
    int rel = td.x, start = td.y, cnt = td.z;

    if (rel >= 0) {
        const uint4* bbase = g_bfrag + (size_t)rel * 4096 + l;

        // prefetch B half0 of ks=0 immediately (hidden under the gather phase)
        uint4 b0[8], b1[8];
        #pragma unroll
        for (int nt = 0; nt < 8; nt++) b0[nt] = bbase[nt * 32];

        rsh[tid] = rel_emb[rel * D + tid];

        // warp-local bucket read (lanes 0-7 hold rows w*8..w*8+7)
        int4 b4 = make_int4(0, 0, 0, 0);
        if (l < 8 && w * 8 + l < cnt)
            b4 = g_bucket4[rel * M_TOT + start + w * 8 + l];
        if (l < 8 && w * 8 + l < cnt) msh[w * 8 + l] = b4.x;

        // ---- gather + bf16 split + stage A (u at row m, v at row 32+m) ----
        float sqa[8];
        #pragma unroll
        for (int it = 0; it < 8; it++) {
            int m = w * 8 + it;
            int hm = __shfl_sync(0xffffffffu, b4.y, it);
            int pm = __shfl_sync(0xffffffffu, b4.z, it);
            int nm = __shfl_sync(0xffffffffu, b4.w, it);
            char* puh = smem + OFF_AHI + m * ASTRIDE + 8 * l;
            char* pul = smem + OFF_ALO + m * ASTRIDE + 8 * l;
            char* pvh = smem + OFF_AHI + (TM + m) * ASTRIDE + 8 * l;
            char* pvl = smem + OFF_ALO + (TM + m) * ASTRIDE + 8 * l;
            float sq = 0.f;
            if (m < cnt) {
                float4 h4 = ((const float4*)(ent + (size_t)hm * D))[l];
                float4 p4 = ((const float4*)(ent + (size_t)pm * D))[l];
                float4 n4 = ((const float4*)(ent + (size_t)nm * D))[l];
                float u0 = h4.x - p4.x, u1 = h4.y - p4.y, u2 = h4.z - p4.z, u3 = h4.w - p4.w;
                float v0 = h4.x - n4.x, v1 = h4.y - n4.y, v2 = h4.z - n4.z, v3 = h4.w - n4.w;
                sq = h4.x*h4.x + h4.y*h4.y + h4.z*h4.z + h4.w*h4.w
                   + p4.x*p4.x + p4.y*p4.y + p4.z*p4.z + p4.w*p4.w
                   + n4.x*n4.x + n4.y*n4.y + n4.z*n4.z + n4.w*n4.w;
                unsigned short uh[4], ul[4], vh[4], vl[4];
                split_bf(u0, uh[0], ul[0]); split_bf(u1, uh[1], ul[1]);
                split_bf(u2, uh[2], ul[2]); split_bf(u3, uh[3], ul[3]);
                split_bf(v0, vh[0], vl[0]); split_bf(v1, vh[1], vl[1]);
                split_bf(v2, vh[2], vl[2]); split_bf(v3, vh[3], vl[3]);
                *(uint2*)puh = make_uint2((uint32_t)uh[0] | ((uint32_t)uh[1] << 16),
                                          (uint32_t)uh[2] | ((uint32_t)uh[3] << 16));
                *(uint2*)pul = make_uint2((uint32_t)ul[0] | ((uint32_t)ul[1] << 16),
                                          (uint32_t)ul[2] | ((uint32_t)ul[3] << 16));
                *(uint2*)pvh = make_uint2((uint32_t)vh[0] | ((uint32_t)vh[1] << 16),
                                          (uint32_t)vh[2] | ((uint32_t)vh[3] << 16));
                *(uint2*)pvl = make_uint2((uint32_t)vl[0] | ((uint32_t)vl[1] << 16),
                                          (uint32_t)vl[2] | ((uint32_t)vl[3] << 16));
            } else {
                uint2 z = make_uint2(0u, 0u);
                *(uint2*)puh = z; *(uint2*)pul = z;
                *(uint2*)pvh = z; *(uint2*)pvl = z;
            }
            sqa[it] = sq;
        }
        // reg squares
        #pragma unroll
        for (int it = 0; it < 8; it++) {
            float s = sqa[it];
            #pragma unroll
            for (int o = 16; o; o >>= 1) s += __shfl_xor_sync(0xffffffffu, s, o);
            if (l == 0) regsh[w * 8 + it] = s;
        }
        __syncthreads();

        // ---- MMA: warp w computes rows 16w..16w+15 (3-pass bf16 split), pipelined B ----
        const char* A0h = smem + OFF_AHI + (16 * w + gid) * ASTRIDE + 4 * tig;
        const char* A1h = A0h + 8 * ASTRIDE;
        const char* A0l = smem + OFF_ALO + (16 * w + gid) * ASTRIDE + 4 * tig;
        const char* A1l = A0l + 8 * ASTRIDE;

        float c[16][4];
        #pragma unroll
        for (int nt = 0; nt < 16; nt++)
            #pragma unroll
            for (int i = 0; i < 4; i++) c[nt][i] = 0.f;

        #pragma unroll
        for (int ks = 0; ks < 8; ks++) {
            uint32_t ah0 = *(const uint32_t*)(A0h + 32 * ks);
            uint32_t ah1 = *(const uint32_t*)(A1h + 32 * ks);
            uint32_t ah2 = *(const uint32_t*)(A0h + 32 * ks + 16);
            uint32_t ah3 = *(const uint32_t*)(A1h + 32 * ks + 16);
            uint32_t al0 = *(const uint32_t*)(A0l + 32 * ks);
            uint32_t al1 = *(const uint32_t*)(A1l + 32 * ks);
            uint32_t al2 = *(const uint32_t*)(A0l + 32 * ks + 16);
            uint32_t al3 = *(const uint32_t*)(A1l + 32 * ks + 16);

            // prefetch half1 (nt 8..15) of this ks while computing on b0
            #pragma unroll
            for (int nt = 0; nt < 8; nt++) b1[nt] = bbase[(ks * 16 + 8 + nt) * 32];
            #pragma unroll
            for (int nt = 0; nt < 8; nt++) {
                mma_bf16(c[nt], ah0, ah1, ah2, ah3, b0[nt].x, b0[nt].y);
                mma_bf16(c[nt], ah0, ah1, ah2, ah3, b0[nt].z, b0[nt].w);
                mma_bf16(c[nt], al0, al1, al2, al3, b0[nt].x, b0[nt].y);
            }
            // prefetch half0 of next ks while computing on b1
            if (ks < 7) {
                #pragma unroll
                for (int nt = 0; nt < 8; nt++) b0[nt] = bbase[((ks + 1) * 16 + nt) * 32];
            }
            #pragma unroll
            for (int nt = 0; nt < 8; nt++) {
                mma_bf16(c[8 + nt], ah0, ah1, ah2, ah3, b1[nt].x, b1[nt].y);
                mma_bf16(c[8 + nt], ah0, ah1, ah2, ah3, b1[nt].z, b1[nt].w);
                mma_bf16(c[8 + nt], al0, al1, al2, al3, b1[nt].x, b1[nt].y);
            }
        }

        // ---- epilogue: add r_j, square, reduce over j ----
        float sA = 0.f, sB = 0.f;        // rows 16w+gid, 16w+8+gid
        #pragma unroll
        for (int nt = 0; nt < 16; nt++) {
            float r0 = rsh[8 * nt + 2 * tig];
            float r1 = rsh[8 * nt + 2 * tig + 1];
            float d0 = c[nt][0] + r0, d1 = c[nt][1] + r1;
            float d2 = c[nt][2] + r0, d3 = c[nt][3] + r1;
            sA += d0 * d0 + d1 * d1;
            sB += d2 * d2 + d3 * d3;
        }
        sA += __shfl_xor_sync(0xffffffffu, sA, 1);
        sA += __shfl_xor_sync(0xffffffffu, sA, 2);
        sB += __shfl_xor_sync(0xffffffffu, sB, 1);
        sB += __shfl_xor_sync(0xffffffffu, sB, 2);
        if (tig == 0) {
            sc[16 * w + gid]     = sA;
            sc[16 * w + 8 + gid] = sB;
        }
        __syncthreads();

        if (tid < TM && tid < cnt) {
            float x = 0.5f * (sc[tid] - sc[TM + tid]);              // pos - neg score
            float loss = fmaxf(-x, 0.f) + log1pf(expf(-fabsf(x)));  // softplus(-x)
            g_val[msh[tid]] = loss + REG_LAMBDA * 0.5f * (regsh[tid] + g_rsq[rel]);
        }
    }

    // ---------- last-block deterministic reduction + state reset ----------
    __shared__ bool amLast;
    __threadfence();
    __syncthreads();
    if (tid == 0) {
        unsigned int prev = atomicAdd(&g_done, 1u);
        amLast = (prev == (unsigned int)(gridDim.x - 1));
    }
    __syncthreads();
    if (!amLast) return;
    __threadfence();

    double* sd = (double*)smem;
    double acc = 0.0;
    for (int i = tid; i < M_TOT; i += THREADS) acc += (double)g_val[i];
    sd[tid] = acc;
    __syncthreads();
    for (int s = THREADS / 2; s; s >>= 1) {
        if (tid < s) sd[tid] += sd[tid + s];
        __syncthreads();
    }
    if (tid == 0) out[0] = (float)(sd[0] / (double)M_TOT);

    if (tid < NREL) g_cnt[tid] = 0;
    if (tid == 0) g_done = 0;
}

// ---------------- launch ----------------
extern "C" void kernel_launch(void* const* d_in, const int* in_sizes, int n_in,
                              void* d_out, int out_size) {
    const int*   h       = (const int*)d_in[0];
    const int*   r       = (const int*)d_in[1];
    const int*   pos_t   = (const int*)d_in[2];
    const int*   neg_t   = (const int*)d_in[3];
    const float* ent     = (const float*)d_in[4];
    const float* rel_emb = (const float*)d_in[5];
    const float* rel_w   = (const float*)d_in[6];
    float* out = (float*)d_out;

    cudaFuncSetAttribute(k_prep, cudaFuncAttributeMaxDynamicSharedMemorySize, PREP_SMEM);
    cudaFuncSetAttribute(k_main, cudaFuncAttributeMaxDynamicSharedMemorySize, SMEM_SZ);

    k_prep<<<PREP_BLKS, 256, PREP_SMEM>>>(r, h, pos_t, neg_t, rel_w, rel_emb);
    k_main<<<MAXT, THREADS, SMEM_SZ>>>(ent, rel_emb, out);
}

// round 10
// speedup vs baseline: 1.3266x; 1.1221x over previous
#include <cuda_runtime.h>
#include <cuda_bf16.h>
#include <math.h>
#include <stdint.h>

// Fixed problem shapes
#define M_TOT 8192
#define NREL  64
#define D     128
#define TM    32            // m per tile -> 64 A rows (u rows 0..31, v rows 32..63)
#define MAXT  320
#define THREADS 256
#define REG_LAMBDA 1e-5f

// ---------------- device scratch (zero-init at load; reset each call) ----------------
__device__ int   g_cnt[NREL];
__device__ int4  g_bucket4[NREL * M_TOT];    // {m, h[m], pos[m], neg[m]}
__device__ int4  g_ttab[MAXT];               // {rel, start, cnt, 0}
__device__ float g_rsq[NREL];
__device__ float g_val[M_TOT];
__device__ unsigned int g_done;
__device__ unsigned int g_scat_done;
// B fragments in mma.m16n8k16 register layout:
// g_bfrag[((rel*8 + ks)*16 + nt)*32 + lane] = {b0_hi, b1_hi, b0_lo, b1_lo}
__device__ uint4 g_bfrag[NREL * 8 * 16 * 32];

// ---------------- helpers ----------------
static __device__ __forceinline__ void split_bf(float x, unsigned short& hi, unsigned short& lo) {
    __nv_bfloat16 h = __float2bfloat16(x);
    float hf = __bfloat162float(h);
    __nv_bfloat16 l = __float2bfloat16(x - hf);
    hi = __bfloat16_as_ushort(h);
    lo = __bfloat16_as_ushort(l);
}

static __device__ __forceinline__ void mma_bf16(float c[4],
                                                uint32_t a0, uint32_t a1,
                                                uint32_t a2, uint32_t a3,
                                                uint32_t b0, uint32_t b1) {
    asm("mma.sync.aligned.m16n8k16.row.col.f32.bf16.bf16.f32 "
        "{%0,%1,%2,%3}, {%4,%5,%6,%7}, {%8,%9}, {%0,%1,%2,%3};"
        : "+f"(c[0]), "+f"(c[1]), "+f"(c[2]), "+f"(c[3])
        : "r"(a0), "r"(a1), "r"(a2), "r"(a3), "r"(b0), "r"(b1));
}

// ---------------- prep: scatter+table (blocks 0-31) + W fragments (blocks 32-95) ----------------
#define PREP_BLKS 96
#define PREP_SMEM 65536

__global__ void k_prep(const int* __restrict__ r,
                       const int* __restrict__ h,
                       const int* __restrict__ pos_t,
                       const int* __restrict__ neg_t,
                       const float* __restrict__ rel_w,
                       const float* __restrict__ rel_emb) {
    extern __shared__ char psm[];
    int b = blockIdx.x;
    int tid = threadIdx.x;     // 256 threads

    if (b < 32) {
        int* scnt  = (int*)psm;
        int* sbase = scnt + NREL;
        int* scur  = sbase + NREL;
        if (tid < NREL) { scnt[tid] = 0; scur[tid] = 0; }
        __syncthreads();
        int m  = b * 256 + tid;
        int rl = r[m];
        int hm = h[m], pm = pos_t[m], nm = neg_t[m];
        atomicAdd(&scnt[rl], 1);
        __syncthreads();
        if (tid < NREL && scnt[tid] > 0) sbase[tid] = atomicAdd(&g_cnt[tid], scnt[tid]);
        __syncthreads();
        int p = sbase[rl] + atomicAdd(&scur[rl], 1);
        g_bucket4[rl * M_TOT + p] = make_int4(m, hm, pm, nm);

        __shared__ bool last;
        __threadfence();
        __syncthreads();
        if (tid == 0) last = (atomicAdd(&g_scat_done, 1u) == 31u);
        __syncthreads();
        if (!last) return;
        __threadfence();

        int* stoff = scur + NREL;
        __shared__ int s_ntiles;
        if (tid < NREL) scnt[tid] = g_cnt[tid];
        __syncthreads();
        if (tid == 0) {
            int toff = 0;
            for (int rel = 0; rel < NREL; rel++) {
                stoff[rel] = toff;
                toff += (scnt[rel] + TM - 1) / TM;
            }
            s_ntiles = toff;
            g_scat_done = 0;
        }
        __syncthreads();
        if (tid < NREL) {
            int c = scnt[tid], to = stoff[tid];
            for (int s = 0; s < c; s += TM)
                g_ttab[to++] = make_int4(tid, s, min(TM, c - s), 0);
            float s2 = 0.f;
            const float* re = rel_emb + tid * D;
            #pragma unroll 8
            for (int i = 0; i < D; i++) { float x = re[i]; s2 += x * x; }
            g_rsq[tid] = s2;
        }
        for (int i = s_ntiles + tid; i < MAXT; i += 256)
            g_ttab[i] = make_int4(-1, 0, 0, 0);
        return;
    }

    // ---- W fragment build: one rel per block, staged through smem ----
    {
        int rel = b - 32;
        float* Wsh = (float*)psm;
        const float4* src = (const float4*)(rel_w + (size_t)rel * D * D);
        float4* dst = (float4*)Wsh;
        #pragma unroll
        for (int i = tid; i < D * D / 4; i += 256) dst[i] = src[i];
        __syncthreads();

        #pragma unroll
        for (int q = 0; q < 16; q++) {
            int e = q * 256 + tid;
            int lane = e & 31;
            int nt   = (e >> 5) & 15;
            int ks   = e >> 9;
            int gid = lane >> 2, tig = lane & 3;
            int j  = 8 * nt + gid;
            int k0 = 16 * ks + 2 * tig;
            float w00 = Wsh[k0 * D + j];
            float w01 = Wsh[(k0 + 1) * D + j];
            float w10 = Wsh[(k0 + 8) * D + j];
            float w11 = Wsh[(k0 + 9) * D + j];
            unsigned short h00, l00, h01, l01, h10, l10, h11, l11;
            split_bf(w00, h00, l00); split_bf(w01, h01, l01);
            split_bf(w10, h10, l10); split_bf(w11, h11, l11);
            uint4 v;
            v.x = (uint32_t)h00 | ((uint32_t)h01 << 16);
            v.y = (uint32_t)h10 | ((uint32_t)h11 << 16);
            v.z = (uint32_t)l00 | ((uint32_t)l01 << 16);
            v.w = (uint32_t)l10 | ((uint32_t)l11 << 16);
            g_bfrag[(size_t)rel * 4096 + e] = v;
        }
    }
}

// ---------------- main kernel: 320 blocks x 256 threads (8 warps), 2 blocks/SM ----------------
#define ASTRIDE 264
#define OFF_AHI 0                          // 64*264 = 16896
#define OFF_ALO 16896                      // -> 33792
#define OFF_RSH 33792                      // 512
#define OFF_SC  34304                      // 512 (128 floats: [p*64 + row])
#define OFF_REG 34816                      // 128 (32 floats)
#define OFF_MSH 34944                      // 128
#define SMEM_SZ 35072

__global__ void __launch_bounds__(THREADS, 2) k_main(
    const float* __restrict__ ent,
    const float* __restrict__ rel_emb,
    float*       __restrict__ out)
{
    extern __shared__ char smem[];
    int tid = threadIdx.x;
    int w = tid >> 5, l = tid & 31;
    int g = w >> 1, p = w & 1;           // warp pair (rows), j-half
    int gid = l >> 2, tig = l & 3;

    float* rsh   = (float*)(smem + OFF_RSH);
    float* sc    = (float*)(smem + OFF_SC);
    float* regsh = (float*)(smem + OFF_REG);
    int*   msh   = (int*)(smem + OFF_MSH);

    int4 td = g_ttab[blockIdx.x];
    int rel = td.x, start = td.y, cnt = td.z;

    if (rel >= 0) {
        if (tid < D) rsh[tid] = rel_emb[rel * D + tid];

        // warp-local bucket read: lanes 0-3 hold rows w*4..w*4+3
        int4 b4 = make_int4(0, 0, 0, 0);
        if (l < 4 && w * 4 + l < cnt)
            b4 = g_bucket4[rel * M_TOT + start + w * 4 + l];
        if (l < 4 && w * 4 + l < cnt) msh[w * 4 + l] = b4.x;

        // ---- gather + bf16 split + stage A (u at row m, v at row 32+m); 4 rows/warp ----
        float sqa[4];
        #pragma unroll
        for (int it = 0; it < 4; it++) {
            int m = w * 4 + it;
            int hm = __shfl_sync(0xffffffffu, b4.y, it);
            int pm = __shfl_sync(0xffffffffu, b4.z, it);
            int nm = __shfl_sync(0xffffffffu, b4.w, it);
            char* puh = smem + OFF_AHI + m * ASTRIDE + 8 * l;
            char* pul = smem + OFF_ALO + m * ASTRIDE + 8 * l;
            char* pvh = smem + OFF_AHI + (TM + m) * ASTRIDE + 8 * l;
            char* pvl = smem + OFF_ALO + (TM + m) * ASTRIDE + 8 * l;
            float sq = 0.f;
            if (m < cnt) {
                float4 h4 = ((const float4*)(ent + (size_t)hm * D))[l];
                float4 p4 = ((const float4*)(ent + (size_t)pm * D))[l];
                float4 n4 = ((const float4*)(ent + (size_t)nm * D))[l];
                float u0 = h4.x - p4.x, u1 = h4.y - p4.y, u2 = h4.z - p4.z, u3 = h4.w - p4.w;
                float v0 = h4.x - n4.x, v1 = h4.y - n4.y, v2 = h4.z - n4.z, v3 = h4.w - n4.w;
                sq = h4.x*h4.x + h4.y*h4.y + h4.z*h4.z + h4.w*h4.w
                   + p4.x*p4.x + p4.y*p4.y + p4.z*p4.z + p4.w*p4.w
                   + n4.x*n4.x + n4.y*n4.y + n4.z*n4.z + n4.w*n4.w;
                unsigned short uh[4], ul[4], vh[4], vl[4];
                split_bf(u0, uh[0], ul[0]); split_bf(u1, uh[1], ul[1]);
                split_bf(u2, uh[2], ul[2]); split_bf(u3, uh[3], ul[3]);
                split_bf(v0, vh[0], vl[0]); split_bf(v1, vh[1], vl[1]);
                split_bf(v2, vh[2], vl[2]); split_bf(v3, vh[3], vl[3]);
                *(uint2*)puh = make_uint2((uint32_t)uh[0] | ((uint32_t)uh[1] << 16),
                                          (uint32_t)uh[2] | ((uint32_t)uh[3] << 16));
                *(uint2*)pul = make_uint2((uint32_t)ul[0] | ((uint32_t)ul[1] << 16),
                                          (uint32_t)ul[2] | ((uint32_t)ul[3] << 16));
                *(uint2*)pvh = make_uint2((uint32_t)vh[0] | ((uint32_t)vh[1] << 16),
                                          (uint32_t)vh[2] | ((uint32_t)vh[3] << 16));
                *(uint2*)pvl = make_uint2((uint32_t)vl[0] | ((uint32_t)vl[1] << 16),
                                          (uint32_t)vl[2] | ((uint32_t)vl[3] << 16));
            } else {
                uint2 z = make_uint2(0u, 0u);
                *(uint2*)puh = z; *(uint2*)pul = z;
                *(uint2*)pvh = z; *(uint2*)pvl = z;
            }
            sqa[it] = sq;
        }
        #pragma unroll
        for (int it = 0; it < 4; it++) {
            float s = sqa[it];
            #pragma unroll
            for (int o = 16; o; o >>= 1) s += __shfl_xor_sync(0xffffffffu, s, o);
            if (l == 0) regsh[w * 4 + it] = s;
        }
        __syncthreads();

        // ---- MMA: warp (g,p) computes rows 16g..16g+15, nt = 8p..8p+7 (3-pass split) ----
        const char* A0h = smem + OFF_AHI + (16 * g + gid) * ASTRIDE + 4 * tig;
        const char* A1h = A0h + 8 * ASTRIDE;
        const char* A0l = smem + OFF_ALO + (16 * g + gid) * ASTRIDE + 4 * tig;
        const char* A1l = A0l + 8 * ASTRIDE;
        const uint4* bbase = g_bfrag + (size_t)rel * 4096 + (8 * p) * 32 + l;

        float c[8][4];
        #pragma unroll
        for (int nt = 0; nt < 8; nt++)
            #pragma unroll
            for (int i = 0; i < 4; i++) c[nt][i] = 0.f;

        for (int ks = 0; ks < 8; ks++) {
            uint32_t ah0 = *(const uint32_t*)(A0h + 32 * ks);
            uint32_t ah1 = *(const uint32_t*)(A1h + 32 * ks);
            uint32_t ah2 = *(const uint32_t*)(A0h + 32 * ks + 16);
            uint32_t ah3 = *(const uint32_t*)(A1h + 32 * ks + 16);
            uint32_t al0 = *(const uint32_t*)(A0l + 32 * ks);
            uint32_t al1 = *(const uint32_t*)(A1l + 32 * ks);
            uint32_t al2 = *(const uint32_t*)(A0l + 32 * ks + 16);
            uint32_t al3 = *(const uint32_t*)(A1l + 32 * ks + 16);

            const uint4* bp = bbase + (size_t)ks * 16 * 32;
            uint4 b[8];
            #pragma unroll
            for (int nt = 0; nt < 8; nt++) b[nt] = bp[nt * 32];   // MLP=8, L1/L2-hot

            #pragma unroll
            for (int nt = 0; nt < 8; nt++) {
                mma_bf16(c[nt], ah0, ah1, ah2, ah3, b[nt].x, b[nt].y);
                mma_bf16(c[nt], ah0, ah1, ah2, ah3, b[nt].z, b[nt].w);
                mma_bf16(c[nt], al0, al1, al2, al3, b[nt].x, b[nt].y);
            }
        }

        // ---- epilogue: add r_j, square, reduce over this warp's 64 j's ----
        float sA = 0.f, sB = 0.f;        // rows 16g+gid, 16g+8+gid
        #pragma unroll
        for (int i = 0; i < 8; i++) {
            int nt = 8 * p + i;
            float r0 = rsh[8 * nt + 2 * tig];
            float r1 = rsh[8 * nt + 2 * tig + 1];
            float d0 = c[i][0] + r0, d1 = c[i][1] + r1;
            float d2 = c[i][2] + r0, d3 = c[i][3] + r1;
            sA += d0 * d0 + d1 * d1;
            sB += d2 * d2 + d3 * d3;
        }
        sA += __shfl_xor_sync(0xffffffffu, sA, 1);
        sA += __shfl_xor_sync(0xffffffffu, sA, 2);
        sB += __shfl_xor_sync(0xffffffffu, sB, 1);
        sB += __shfl_xor_sync(0xffffffffu, sB, 2);
        if (tig == 0) {
            sc[p * 64 + 16 * g + gid]     = sA;
            sc[p * 64 + 16 * g + 8 + gid] = sB;
        }
        __syncthreads();

        if (tid < TM && tid < cnt) {
            float pos = sc[tid]      + sc[64 + tid];        // u row: both j-halves
            float neg = sc[TM + tid] + sc[64 + TM + tid];   // v row
            float x = 0.5f * (pos - neg);
            float loss = fmaxf(-x, 0.f) + log1pf(expf(-fabsf(x)));  // softplus(-x)
            g_val[msh[tid]] = loss + REG_LAMBDA * 0.5f * (regsh[tid] + g_rsq[rel]);
        }
    }

    // ---------- last-block deterministic reduction + state reset ----------
    __shared__ bool amLast;
    __threadfence();
    __syncthreads();
    if (tid == 0) {
        unsigned int prev = atomicAdd(&g_done, 1u);
        amLast = (prev == (unsigned int)(gridDim.x - 1));
    }
    __syncthreads();
    if (!amLast) return;
    __threadfence();

    double* sd = (double*)smem;
    double acc = 0.0;
    for (int i = tid; i < M_TOT; i += THREADS) acc += (double)g_val[i];
    sd[tid] = acc;
    __syncthreads();
    for (int s = THREADS / 2; s; s >>= 1) {
        if (tid < s) sd[tid] += sd[tid + s];
        __syncthreads();
    }
    if (tid == 0) out[0] = (float)(sd[0] / (double)M_TOT);

    if (tid < NREL) g_cnt[tid] = 0;
    if (tid == 0) g_done = 0;
}

// ---------------- launch ----------------
extern "C" void kernel_launch(void* const* d_in, const int* in_sizes, int n_in,
                              void* d_out, int out_size) {
    const int*   h       = (const int*)d_in[0];
    const int*   r       = (const int*)d_in[1];
    const int*   pos_t   = (const int*)d_in[2];
    const int*   neg_t   = (const int*)d_in[3];
    const float* ent     = (const float*)d_in[4];
    const float* rel_emb = (const float*)d_in[5];
    const float* rel_w   = (const float*)d_in[6];
    float* out = (float*)d_out;

    cudaFuncSetAttribute(k_prep, cudaFuncAttributeMaxDynamicSharedMemorySize, PREP_SMEM);
    cudaFuncSetAttribute(k_main, cudaFuncAttributeMaxDynamicSharedMemorySize, SMEM_SZ);

    k_prep<<<PREP_BLKS, 256, PREP_SMEM>>>(r, h, pos_t, neg_t, rel_w, rel_emb);
    k_main<<<MAXT, THREADS, SMEM_SZ>>>(ent, rel_emb, out);
}

// round 11
// speedup vs baseline: 1.5234x; 1.1484x over previous
#include <cuda_runtime.h>
#include <cuda_bf16.h>
#include <math.h>
#include <stdint.h>

// Fixed problem shapes
#define M_TOT 8192
#define NREL  64
#define D     128
#define TM    32            // m per tile -> 64 A rows (u rows 0..31, v rows 32..63)
#define THREADS 256
#define NBLK  296           // 2 blocks/SM x 148 SMs, all resident -> safe grid barrier
#define REG_LAMBDA 1e-5f

// ---------------- device scratch (zero-init at load; reset at end of each call) ----------------
__device__ int   g_cnt[NREL];
__device__ int4  g_bucket4[NREL * M_TOT];    // {m, h[m], pos[m], neg[m]}
__device__ float g_rsq[NREL];
__device__ float g_val[M_TOT];
__device__ unsigned int g_done;
__device__ unsigned int g_bar;
__device__ unsigned int g_tilectr;
// B fragments in mma.m16n8k16 register layout:
// g_bfrag[((rel*8 + ks)*16 + nt)*32 + lane] = {b0_hi, b1_hi, b0_lo, b1_lo}
__device__ uint4 g_bfrag[NREL * 8 * 16 * 32];

// ---------------- helpers ----------------
static __device__ __forceinline__ void split_bf(float x, unsigned short& hi, unsigned short& lo) {
    __nv_bfloat16 h = __float2bfloat16(x);
    float hf = __bfloat162float(h);
    __nv_bfloat16 l = __float2bfloat16(x - hf);
    hi = __bfloat16_as_ushort(h);
    lo = __bfloat16_as_ushort(l);
}

static __device__ __forceinline__ void mma_bf16(float c[4],
                                                uint32_t a0, uint32_t a1,
                                                uint32_t a2, uint32_t a3,
                                                uint32_t b0, uint32_t b1) {
    asm("mma.sync.aligned.m16n8k16.row.col.f32.bf16.bf16.f32 "
        "{%0,%1,%2,%3}, {%4,%5,%6,%7}, {%8,%9}, {%0,%1,%2,%3};"
        : "+f"(c[0]), "+f"(c[1]), "+f"(c[2]), "+f"(c[3])
        : "r"(a0), "r"(a1), "r"(a2), "r"(a3), "r"(b0), "r"(b1));
}

// ---------------- smem layout (single 64 KB dynamic buffer) ----------------
// Phase-1 frag build uses the whole buffer as Wsh[128*128] floats.
// Phase-2 tile body uses:
#define ASTRIDE 264
#define OFF_AHI 0                          // 64*264 = 16896
#define OFF_ALO 16896                      // -> 33792
#define OFF_RSH 33792                      // 512
#define OFF_SC  34304                      // 512 (128 floats: [p*64 + row])
#define OFF_REG 34816                      // 128 (32 floats)
#define OFF_MSH 34944                      // 128 -> 35072
#define OFF_SCNT 35072                     // 64 ints
#define OFF_STP  35328                     // 65 ints -> 35588
#define OFF_CTL  35600                     // {rel, start, cnt}
#define SMEM_SZ  65536

__global__ void __launch_bounds__(THREADS, 2) k_all(
    const int*   __restrict__ r,
    const int*   __restrict__ h,
    const int*   __restrict__ pos_t,
    const int*   __restrict__ neg_t,
    const float* __restrict__ ent,
    const float* __restrict__ rel_emb,
    const float* __restrict__ rel_w,
    float*       __restrict__ out)
{
    extern __shared__ char smem[];
    int b   = blockIdx.x;
    int tid = threadIdx.x;
    int w = tid >> 5, l = tid & 31;
    int g = w >> 1, p = w & 1;           // warp pair (rows), j-half
    int gid = l >> 2, tig = l & 3;

    // ================= Phase 1: scatter (blocks 0-31) / W fragments (32-95) =================
    if (b < 32) {
        int* scnt  = (int*)smem;
        int* sbase = scnt + NREL;
        int* scur  = sbase + NREL;
        if (tid < NREL) { scnt[tid] = 0; scur[tid] = 0; }
        __syncthreads();
        int m  = b * 256 + tid;
        int rl = r[m];
        int hm = h[m], pm = pos_t[m], nm = neg_t[m];
        atomicAdd(&scnt[rl], 1);
        __syncthreads();
        if (tid < NREL && scnt[tid] > 0) sbase[tid] = atomicAdd(&g_cnt[tid], scnt[tid]);
        __syncthreads();
        int pp = sbase[rl] + atomicAdd(&scur[rl], 1);
        g_bucket4[rl * M_TOT + pp] = make_int4(m, hm, pm, nm);
        // per-rel rsq: block 0 computes it (64 rows x 128) - cheap, overlapped with other blocks
        if (b == 0) {
            for (int rel = w; rel < NREL; rel += 8) {
                float s = 0.f;
                const float4* re = (const float4*)(rel_emb + rel * D);
                float4 v = re[l];
                s = v.x * v.x + v.y * v.y + v.z * v.z + v.w * v.w;
                #pragma unroll
                for (int o = 16; o; o >>= 1) s += __shfl_xor_sync(0xffffffffu, s, o);
                if (l == 0) g_rsq[rel] = s;
            }
        }
    } else if (b < 96) {
        int rel = b - 32;
        float* Wsh = (float*)smem;          // 64 KB: W[k][j]
        const float4* src = (const float4*)(rel_w + (size_t)rel * D * D);
        float4* dst = (float4*)Wsh;
        #pragma unroll
        for (int i = tid; i < D * D / 4; i += 256) dst[i] = src[i];   // coalesced
        __syncthreads();
        #pragma unroll
        for (int q = 0; q < 16; q++) {
            int e = q * 256 + tid;
            int lane = e & 31;
            int nt   = (e >> 5) & 15;
            int ks   = e >> 9;
            int gg = lane >> 2, tt = lane & 3;
            int j  = 8 * nt + gg;
            int k0 = 16 * ks + 2 * tt;
            float w00 = Wsh[k0 * D + j];
            float w01 = Wsh[(k0 + 1) * D + j];
            float w10 = Wsh[(k0 + 8) * D + j];
            float w11 = Wsh[(k0 + 9) * D + j];
            unsigned short h00, l00, h01, l01, h10, l10, h11, l11;
            split_bf(w00, h00, l00); split_bf(w01, h01, l01);
            split_bf(w10, h10, l10); split_bf(w11, h11, l11);
            uint4 v;
            v.x = (uint32_t)h00 | ((uint32_t)h01 << 16);
            v.y = (uint32_t)h10 | ((uint32_t)h11 << 16);
            v.z = (uint32_t)l00 | ((uint32_t)l01 << 16);
            v.w = (uint32_t)l10 | ((uint32_t)l11 << 16);
            g_bfrag[(size_t)rel * 4096 + e] = v;     // coalesced STG.128
        }
    }

    // ================= Grid barrier (all 296 blocks resident) =================
    __threadfence();
    __syncthreads();
    if (tid == 0) {
        atomicAdd(&g_bar, 1u);
        while (atomicAdd(&g_bar, 0u) < NBLK) __nanosleep(32);
    }
    __syncthreads();

    // ================= Phase 2: per-block plan + tile loop =================
    float* rsh   = (float*)(smem + OFF_RSH);
    float* sc    = (float*)(smem + OFF_SC);
    float* regsh = (float*)(smem + OFF_REG);
    int*   msh   = (int*)(smem + OFF_MSH);
    int*   scnt  = (int*)(smem + OFF_SCNT);
    int*   stp   = (int*)(smem + OFF_STP);

    if (tid < NREL) scnt[tid] = g_cnt[tid];
    __syncthreads();
    if (tid == 0) {
        int acc = 0;
        for (int rel = 0; rel < NREL; rel++) {
            stp[rel] = acc;
            acc += (scnt[rel] + TM - 1) / TM;
        }
        stp[NREL] = acc;
    }
    __syncthreads();
    int ntiles = stp[NREL];

    for (;;) {
        if (tid == 0) {
            int tile = (int)atomicAdd(&g_tilectr, 1u);
            int rel = -1, start = 0, cnt = 0;
            if (tile < ntiles) {
                rel = 0;
                while (stp[rel + 1] <= tile) rel++;
                start = (tile - stp[rel]) * TM;
                cnt = min(TM, scnt[rel] - start);
            }
            ((int*)(smem + OFF_CTL))[0] = rel;
            ((int*)(smem + OFF_CTL))[1] = start;
            ((int*)(smem + OFF_CTL))[2] = cnt;
        }
        __syncthreads();
        int rel   = ((int*)(smem + OFF_CTL))[0];
        int start = ((int*)(smem + OFF_CTL))[1];
        int cnt   = ((int*)(smem + OFF_CTL))[2];
        if (rel < 0) break;

        if (tid < D) rsh[tid] = rel_emb[rel * D + tid];

        // warp-local bucket read: lanes 0-3 hold rows w*4..w*4+3
        int4 b4 = make_int4(0, 0, 0, 0);
        if (l < 4 && w * 4 + l < cnt)
            b4 = g_bucket4[rel * M_TOT + start + w * 4 + l];
        if (l < 4 && w * 4 + l < cnt) msh[w * 4 + l] = b4.x;

        // ---- gather + bf16 split + stage A (u at row m, v at row 32+m); 4 rows/warp ----
        float sqa[4];
        #pragma unroll
        for (int it = 0; it < 4; it++) {
            int m = w * 4 + it;
            int hm = __shfl_sync(0xffffffffu, b4.y, it);
            int pm = __shfl_sync(0xffffffffu, b4.z, it);
            int nm = __shfl_sync(0xffffffffu, b4.w, it);
            char* puh = smem + OFF_AHI + m * ASTRIDE + 8 * l;
            char* pul = smem + OFF_ALO + m * ASTRIDE + 8 * l;
            char* pvh = smem + OFF_AHI + (TM + m) * ASTRIDE + 8 * l;
            char* pvl = smem + OFF_ALO + (TM + m) * ASTRIDE + 8 * l;
            float sq = 0.f;
            if (m < cnt) {
                float4 h4 = ((const float4*)(ent + (size_t)hm * D))[l];
                float4 p4 = ((const float4*)(ent + (size_t)pm * D))[l];
                float4 n4 = ((const float4*)(ent + (size_t)nm * D))[l];
                float u0 = h4.x - p4.x, u1 = h4.y - p4.y, u2 = h4.z - p4.z, u3 = h4.w - p4.w;
                float v0 = h4.x - n4.x, v1 = h4.y - n4.y, v2 = h4.z - n4.z, v3 = h4.w - n4.w;
                sq = h4.x*h4.x + h4.y*h4.y + h4.z*h4.z + h4.w*h4.w
                   + p4.x*p4.x + p4.y*p4.y + p4.z*p4.z + p4.w*p4.w
                   + n4.x*n4.x + n4.y*n4.y + n4.z*n4.z + n4.w*n4.w;
                unsigned short uh[4], ul[4], vh[4], vl[4];
                split_bf(u0, uh[0], ul[0]); split_bf(u1, uh[1], ul[1]);
                split_bf(u2, uh[2], ul[2]); split_bf(u3, uh[3], ul[3]);
                split_bf(v0, vh[0], vl[0]); split_bf(v1, vh[1], vl[1]);
                split_bf(v2, vh[2], vl[2]); split_bf(v3, vh[3], vl[3]);
                *(uint2*)puh = make_uint2((uint32_t)uh[0] | ((uint32_t)uh[1] << 16),
                                          (uint32_t)uh[2] | ((uint32_t)uh[3] << 16));
                *(uint2*)pul = make_uint2((uint32_t)ul[0] | ((uint32_t)ul[1] << 16),
                                          (uint32_t)ul[2] | ((uint32_t)ul[3] << 16));
                *(uint2*)pvh = make_uint2((uint32_t)vh[0] | ((uint32_t)vh[1] << 16),
                                          (uint32_t)vh[2] | ((uint32_t)vh[3] << 16));
                *(uint2*)pvl = make_uint2((uint32_t)vl[0] | ((uint32_t)vl[1] << 16),
                                          (uint32_t)vl[2] | ((uint32_t)vl[3] << 16));
            } else {
                uint2 z = make_uint2(0u, 0u);
                *(uint2*)puh = z; *(uint2*)pul = z;
                *(uint2*)pvh = z; *(uint2*)pvl = z;
            }
            sqa[it] = sq;
        }
        #pragma unroll
        for (int it = 0; it < 4; it++) {
            float s = sqa[it];
            #pragma unroll
            for (int o = 16; o; o >>= 1) s += __shfl_xor_sync(0xffffffffu, s, o);
            if (l == 0) regsh[w * 4 + it] = s;
        }
        __syncthreads();

        // ---- MMA: warp (g,p) computes rows 16g..16g+15, nt = 8p..8p+7 (3-pass split) ----
        const char* A0h = smem + OFF_AHI + (16 * g + gid) * ASTRIDE + 4 * tig;
        const char* A1h = A0h + 8 * ASTRIDE;
        const char* A0l = smem + OFF_ALO + (16 * g + gid) * ASTRIDE + 4 * tig;
        const char* A1l = A0l + 8 * ASTRIDE;
        const uint4* bbase = g_bfrag + (size_t)rel * 4096 + (8 * p) * 32 + l;

        float c[8][4];
        #pragma unroll
        for (int nt = 0; nt < 8; nt++)
            #pragma unroll
            for (int i = 0; i < 4; i++) c[nt][i] = 0.f;

        for (int ks = 0; ks < 8; ks++) {
            uint32_t ah0 = *(const uint32_t*)(A0h + 32 * ks);
            uint32_t ah1 = *(const uint32_t*)(A1h + 32 * ks);
            uint32_t ah2 = *(const uint32_t*)(A0h + 32 * ks + 16);
            uint32_t ah3 = *(const uint32_t*)(A1h + 32 * ks + 16);
            uint32_t al0 = *(const uint32_t*)(A0l + 32 * ks);
            uint32_t al1 = *(const uint32_t*)(A1l + 32 * ks);
            uint32_t al2 = *(const uint32_t*)(A0l + 32 * ks + 16);
            uint32_t al3 = *(const uint32_t*)(A1l + 32 * ks + 16);

            const uint4* bp = bbase + (size_t)ks * 16 * 32;
            uint4 bb[8];
            #pragma unroll
            for (int nt = 0; nt < 8; nt++) bb[nt] = bp[nt * 32];   // MLP=8, L2-hot

            #pragma unroll
            for (int nt = 0; nt < 8; nt++) {
                mma_bf16(c[nt], ah0, ah1, ah2, ah3, bb[nt].x, bb[nt].y);
                mma_bf16(c[nt], ah0, ah1, ah2, ah3, bb[nt].z, bb[nt].w);
                mma_bf16(c[nt], al0, al1, al2, al3, bb[nt].x, bb[nt].y);
            }
        }

        // ---- epilogue: add r_j, square, reduce over this warp's 64 j's ----
        float sA = 0.f, sB = 0.f;        // rows 16g+gid, 16g+8+gid
        #pragma unroll
        for (int i = 0; i < 8; i++) {
            int nt = 8 * p + i;
            float r0 = rsh[8 * nt + 2 * tig];
            float r1 = rsh[8 * nt + 2 * tig + 1];
            float d0 = c[i][0] + r0, d1 = c[i][1] + r1;
            float d2 = c[i][2] + r0, d3 = c[i][3] + r1;
            sA += d0 * d0 + d1 * d1;
            sB += d2 * d2 + d3 * d3;
        }
        sA += __shfl_xor_sync(0xffffffffu, sA, 1);
        sA += __shfl_xor_sync(0xffffffffu, sA, 2);
        sB += __shfl_xor_sync(0xffffffffu, sB, 1);
        sB += __shfl_xor_sync(0xffffffffu, sB, 2);
        if (tig == 0) {
            sc[p * 64 + 16 * g + gid]     = sA;
            sc[p * 64 + 16 * g + 8 + gid] = sB;
        }
        __syncthreads();

        if (tid < TM && tid < cnt) {
            float pos = sc[tid]      + sc[64 + tid];        // u row: both j-halves
            float neg = sc[TM + tid] + sc[64 + TM + tid];   // v row
            float x = 0.5f * (pos - neg);
            float loss = fmaxf(-x, 0.f) + log1pf(expf(-fabsf(x)));  // softplus(-x)
            g_val[msh[tid]] = loss + REG_LAMBDA * 0.5f * (regsh[tid] + g_rsq[rel]);
        }
        __syncthreads();
    }

    // ---------- last-block deterministic reduction + state reset ----------
    __shared__ bool amLast;
    __threadfence();
    __syncthreads();
    if (tid == 0) {
        unsigned int prev = atomicAdd(&g_done, 1u);
        amLast = (prev == (unsigned int)(gridDim.x - 1));
    }
    __syncthreads();
    if (!amLast) return;
    __threadfence();

    double* sd = (double*)smem;
    double acc = 0.0;
    for (int i = tid; i < M_TOT; i += THREADS) acc += (double)g_val[i];
    sd[tid] = acc;
    __syncthreads();
    for (int s = THREADS / 2; s; s >>= 1) {
        if (tid < s) sd[tid] += sd[tid + s];
        __syncthreads();
    }
    if (tid == 0) out[0] = (float)(sd[0] / (double)M_TOT);

    if (tid < NREL) g_cnt[tid] = 0;
    if (tid == 0) { g_done = 0; g_bar = 0; g_tilectr = 0; }
}

// ---------------- launch ----------------
extern "C" void kernel_launch(void* const* d_in, const int* in_sizes, int n_in,
                              void* d_out, int out_size) {
    const int*   h       = (const int*)d_in[0];
    const int*   r       = (const int*)d_in[1];
    const int*   pos_t   = (const int*)d_in[2];
    const int*   neg_t   = (const int*)d_in[3];
    const float* ent     = (const float*)d_in[4];
    const float* rel_emb = (const float*)d_in[5];
    const float* rel_w   = (const float*)d_in[6];
    float* out = (float*)d_out;

    cudaFuncSetAttribute(k_all, cudaFuncAttributeMaxDynamicSharedMemorySize, SMEM_SZ);
    k_all<<<NBLK, THREADS, SMEM_SZ>>>(r, h, pos_t, neg_t, ent, rel_emb, rel_w, out);
}